// round 5
// baseline (speedup 1.0000x reference)
#include <cuda_runtime.h>
#include <cstdint>

// PANNAcceptor: out[b] = lin_w @ (W[x_{L-1}] ... W[x_0] e0) + lin_b
// Round 5: length-aware hybrid.
//   Short batches (L <= THRESH): solo CTA, R1-style streaming loop, zero
//     cluster-sync overhead; peer CTA exits immediately.
//   Long batches  (L > THRESH): 2-CTA row-split with mbarrier ping-pong
//     handoff (R4 protocol, arrivals halved) -> ~2x step rate on the
//     straggler tail that bounds total runtime.

#define NST    256
#define TPB    512     // 16 warps
#define HALF   128
#define THRESH 512

__device__ __forceinline__ uint32_t smem_u32(const void* p) {
    uint32_t a;
    asm("{ .reg .u64 t; cvta.to.shared.u64 t, %1; cvt.u32.u64 %0, t; }" : "=r"(a) : "l"(p));
    return a;
}
__device__ __forceinline__ uint32_t mapa_u32(uint32_t a, uint32_t rank) {
    uint32_t r;
    asm("mapa.shared::cluster.u32 %0, %1, %2;" : "=r"(r) : "r"(a), "r"(rank));
    return r;
}
__device__ __forceinline__ void st_remote_f32(uint32_t ra, float v) {
    asm volatile("st.shared::cluster.f32 [%0], %1;" :: "r"(ra), "f"(v) : "memory");
}
__device__ __forceinline__ void mbar_init(uint32_t a, uint32_t n) {
    asm volatile("mbarrier.init.shared.b64 [%0], %1;" :: "r"(a), "r"(n) : "memory");
}
__device__ __forceinline__ void mbar_arrive_local(uint32_t a) {
    asm volatile("mbarrier.arrive.release.cluster.shared::cta.b64 _, [%0];" :: "r"(a) : "memory");
}
__device__ __forceinline__ void mbar_arrive_remote(uint32_t ra) {
    asm volatile("mbarrier.arrive.release.cluster.shared::cluster.b64 _, [%0];" :: "r"(ra) : "memory");
}
__device__ __forceinline__ void mbar_wait(uint32_t a, int parity) {
    asm volatile(
        "{\n\t"
        ".reg .pred P;\n\t"
        "W_%=:\n\t"
        "mbarrier.try_wait.parity.acquire.cluster.shared::cta.b64 P, [%0], %1, 0x989680;\n\t"
        "@!P bra W_%=;\n\t"
        "}"
        :: "r"(a), "r"(parity) : "memory");
}
#define CLUSTER_SYNC_() do { \
    asm volatile("barrier.cluster.arrive.aligned;" ::: "memory"); \
    asm volatile("barrier.cluster.wait.aligned;" ::: "memory"); } while (0)

__device__ __forceinline__ float warp_reduce(float v) {
    v += __shfl_xor_sync(0xffffffffu, v, 8);
    v += __shfl_xor_sync(0xffffffffu, v, 4);
    v += __shfl_xor_sync(0xffffffffu, v, 2);
    v += __shfl_xor_sync(0xffffffffu, v, 1);
    return v;
}

__global__ __launch_bounds__(TPB, 2)
__cluster_dims__(2, 1, 1)
void pann_hybrid_kernel(const int* __restrict__ xs,
                        const int* __restrict__ lengths,
                        const float* __restrict__ W,
                        const float* __restrict__ lin_w,
                        const float* __restrict__ lin_b,
                        float* __restrict__ out,
                        int S)
{
    __shared__ float hbuf[2][NST];
    __shared__ alignas(8) unsigned long long mbar[2];

    const int tid  = threadIdx.x;
    const int warp = tid >> 5;
    const int lane = tid & 31;
    const int b    = blockIdx.x >> 1;

    uint32_t rank;
    asm("mov.u32 %0, %%cluster_ctarank;" : "=r"(rank));
    const uint32_t peer   = rank ^ 1u;
    const uint32_t hb_u32 = smem_u32(hbuf);
    const uint32_t mb_u32 = smem_u32(mbar);
    const uint32_t rem_h  = mapa_u32(hb_u32, peer);
    const uint32_t rem_mb = mapa_u32(mb_u32, peer);

    // Split-path arrivals per phase per barrier: lane0 of 16 warps x 2 CTAs = 32.
    if (tid == 0) { mbar_init(mb_u32, 32); mbar_init(mb_u32 + 8, 32); }
    if (tid < NST) hbuf[0][tid] = (tid == 0) ? 1.0f : 0.0f;

    const int L = lengths[b];
    CLUSTER_SYNC_();   // mbar init + h0 visible cluster-wide

    const int* xrow = xs + (size_t)b * S;

    if (L <= THRESH) {
        // ---------------- SOLO PATH (rank 0 only, no cluster sync) ----------------
        if (rank != 0) return;

        int cur = 0;
        const int i0 = warp * 16;     // 16 rows per warp over all 256 rows
        int a = __ldg(xrow);

        for (int t = 0; t < L; ++t) {
            const int a_cur = a;
            if (t + 1 < L) a = __ldg(xrow + t + 1);   // prefetch next symbol

            const float* Wa = W + (size_t)a_cur * (NST * NST);
            const float* hsrc = hbuf[cur];
            float* hdst = hbuf[cur ^ 1];

            const float4 hA = ((const float4*)hsrc)[lane];
            const float4 hB = ((const float4*)hsrc)[32 + lane];

            #pragma unroll 4
            for (int r = 0; r < 16; ++r) {
                const int i = i0 + r;
                const float4* p = (const float4*)(Wa + (size_t)i * NST + lane * 4);
                const float4 wA = p[0];
                const float4 wB = p[32];
                float s = wA.x*hA.x + wA.y*hA.y + wA.z*hA.z + wA.w*hA.w
                        + wB.x*hB.x + wB.y*hB.y + wB.z*hB.z + wB.w*hB.w;
                s += __shfl_xor_sync(0xffffffffu, s, 16);
                s = warp_reduce(s);
                if (lane == 0) hdst[i] = s;
            }
            __syncthreads();
            cur ^= 1;
        }

        const float* hf = hbuf[L & 1];
        if (warp < 2) {
            float s = 0.0f;
            #pragma unroll
            for (int i = lane; i < NST; i += 32)
                s += lin_w[warp * NST + i] * hf[i];
            s += __shfl_xor_sync(0xffffffffu, s, 16);
            s = warp_reduce(s);
            if (lane == 0) out[b * 2 + warp] = s + lin_b[warp];
        }
        return;
    }

    // ---------------- SPLIT PATH (both ranks, mbarrier ping-pong) ----------------
    const int row0 = (int)rank * HALF + warp * 8;   // this warp's 8 rows
    int par0 = 0, par1 = 0;
    int a = __ldg(xrow);

    for (int t = 0; t < L; ++t) {
        const int cur = t & 1;
        const int nxt = cur ^ 1;

        const int a_cur = a;
        if (t + 1 < L) a = __ldg(xrow + t + 1);

        if (t) {   // wait for both halves of h_t
            if (cur) { mbar_wait(mb_u32 + 8, par1); par1 ^= 1; }
            else     { mbar_wait(mb_u32,     par0); par0 ^= 1; }
        }

        const float* Wr = W + (size_t)a_cur * (NST * NST);
        const float* hsrc = hbuf[cur];
        float* hdst = hbuf[nxt];
        const uint32_t rdst = rem_h + (uint32_t)nxt * (NST * 4);

        const float4 hA = ((const float4*)hsrc)[lane];
        const float4 hB = ((const float4*)hsrc)[32 + lane];

        #pragma unroll
        for (int j = 0; j < 8; j += 2) {
            const float4* p0 = (const float4*)(Wr + (size_t)(row0 + j) * NST);
            const float4* p1 = (const float4*)(Wr + (size_t)(row0 + j + 1) * NST);
            const float4 a0 = p0[lane], b0 = p0[32 + lane];
            const float4 a1 = p1[lane], b1 = p1[32 + lane];

            float sA = a0.x*hA.x + a0.y*hA.y + a0.z*hA.z + a0.w*hA.w
                     + b0.x*hB.x + b0.y*hB.y + b0.z*hB.z + b0.w*hB.w;
            float sB = a1.x*hA.x + a1.y*hA.y + a1.z*hA.z + a1.w*hA.w
                     + b1.x*hB.x + b1.y*hB.y + b1.z*hB.z + b1.w*hB.w;

            // fold: lanes<16 reduce row j, lanes>=16 reduce row j+1
            const float oA = __shfl_xor_sync(0xffffffffu, sA, 16);
            const float oB = __shfl_xor_sync(0xffffffffu, sB, 16);
            float v = (lane < 16) ? (sA + oA) : (sB + oB);
            v = warp_reduce(v);                    // lane0: row j, lane16: row j+1
            const float vhi = __shfl_sync(0xffffffffu, v, 16);

            if (lane == 0) {
                const int r = row0 + j;
                hdst[r]     = v;
                hdst[r + 1] = vhi;
                st_remote_f32(rdst + (uint32_t)r * 4,       v);
                st_remote_f32(rdst + (uint32_t)(r + 1) * 4, vhi);
            }
        }

        // one local + one remote arrive per warp (release orders lane0's stores)
        if (lane == 0) {
            const uint32_t off = (uint32_t)nxt * 8;
            mbar_arrive_local(mb_u32 + off);
            mbar_arrive_remote(rem_mb + off);
        }
    }

    CLUSTER_SYNC_();   // all final stores visible

    if (rank == 0 && warp < 2) {
        const float* hf = hbuf[L & 1];
        float s = 0.0f;
        #pragma unroll
        for (int i = lane; i < NST; i += 32)
            s += lin_w[warp * NST + i] * hf[i];
        s += __shfl_xor_sync(0xffffffffu, s, 16);
        s = warp_reduce(s);
        if (lane == 0) out[b * 2 + warp] = s + lin_b[warp];
    }
}

extern "C" void kernel_launch(void* const* d_in, const int* in_sizes, int n_in,
                              void* d_out, int out_size)
{
    const int*   xs      = (const int*)d_in[0];
    const int*   lengths = (const int*)d_in[1];
    const float* W       = (const float*)d_in[2];
    const float* lin_w   = (const float*)d_in[3];
    const float* lin_b   = (const float*)d_in[4];
    float*       out     = (float*)d_out;

    const int B = in_sizes[1];
    const int S = in_sizes[0] / B;

    pann_hybrid_kernel<<<2 * B, TPB>>>(xs, lengths, W, lin_w, lin_b, out, S);
}